// round 5
// baseline (speedup 1.0000x reference)
#include <cuda_runtime.h>
#include <cuda_bf16.h>
#include <cstdint>

// Problem constants (shapes fixed by the dataset)
#define N_NODES_MAX 100000
#define D 64
#define OUT 64
#define LN_EPS 1e-5f

// Scratch: neighbor_sum accumulator [N, D] — device global (no allocs allowed).
// INVARIANT: all-zero at kernel_launch entry. Zero-initialized at module load;
// the gemm kernel re-zeroes every row it consumes, restoring the invariant
// for the next graph replay.
__device__ __align__(16) float g_nsum[N_NODES_MAX * D];

// ---------------------------------------------------------------------------
// Kernel 1: scatter-add. 16 lanes per edge; lane handles float4 chunk `sub`.
// red.global.add.v4.f32: 4 floats per instruction, no return value.
// Dtype detection per-block: if edge_index is int32 pairs read as int64, the
// high halves are ~uniform node indices -> P(256 words all look valid) ~ 0.
// ---------------------------------------------------------------------------
__global__ void __launch_bounds__(256) scatter_kernel(
    const float4* __restrict__ x4,
    const void* __restrict__ ei_raw,
    int n_edges, int n_nodes) {

    const long long* ei64 = reinterpret_cast<const long long*>(ei_raw);
    const int*       ei32 = reinterpret_cast<const int*>(ei_raw);

    // per-block dtype detection (reads first 256 int64 words, L2-cached)
    int bad = 0;
    {
        int nw = n_edges / 2;           // int64 words guaranteed to exist
        if (nw > 256) nw = 256;
        if ((int)threadIdx.x < nw) {
            long long v = ei64[threadIdx.x];
            bad = (v < 0 || v >= (long long)n_nodes) ? 1 : 0;
        }
    }
    const int is64 = !__syncthreads_or(bad);

    const int t   = blockIdx.x * blockDim.x + threadIdx.x;
    const int sub = t & 15;
    int e = t >> 4;
    const int estride = (gridDim.x * blockDim.x) >> 4;
    float4* __restrict__ nsum4 = reinterpret_cast<float4*>(g_nsum);

    if (is64) {
        for (; e < n_edges; e += estride) {
            long long row = ei64[e];
            long long col = ei64[n_edges + e];
            float4 v = x4[row * 16 + sub];
            float4* dst = &nsum4[col * 16 + sub];
            asm volatile("red.global.add.v4.f32 [%0], {%1, %2, %3, %4};"
                         :: "l"(dst), "f"(v.x), "f"(v.y), "f"(v.z), "f"(v.w)
                         : "memory");
        }
    } else {
        for (; e < n_edges; e += estride) {
            long long row = ei32[e];
            long long col = ei32[n_edges + e];
            float4 v = x4[row * 16 + sub];
            float4* dst = &nsum4[col * 16 + sub];
            asm volatile("red.global.add.v4.f32 [%0], {%1, %2, %3, %4};"
                         :: "l"(dst), "f"(v.x), "f"(v.y), "f"(v.z), "f"(v.w)
                         : "memory");
        }
    }
}

// ---------------------------------------------------------------------------
// Kernel 2: fused concat + Linear(128->64) + bias + LayerNorm.
// R2-proven inner loop, scaled up for occupancy:
//   block = 128 nodes x 64 outs, 512 threads, thread tile = 4 nodes x 4 outs.
// A staged transposed [k][n] (64KB); W staged as f32x2 pairs over OUT (32KB).
// Inner loop per k per thread:
//   1x LDS.128 (a: 4 nodes, broadcast)  +  1x LDS.128 (w: 2 f32x2 pairs)
//   4x mov.b64 {a,a}                    +  8x fma.rn.f32x2  (16 FMA lanes)
// smem 96KB -> 2 blocks/SM = 32 warps = 50% occ (vs 35% in R2).
// Also restores the g_nsum all-zero invariant (read-then-clear in staging).
// ---------------------------------------------------------------------------
#define TILE_N 128
#define NTHR   512

__global__ void __launch_bounds__(NTHR, 2) gemm_ln_kernel(
    const float4* __restrict__ x4,
    const float*  __restrict__ W,
    const float*  __restrict__ b,
    const float*  __restrict__ gamma,
    const float*  __restrict__ beta,
    float4* __restrict__ out4,
    int n_nodes) {

    extern __shared__ char smem_raw[];
    float* Ash = reinterpret_cast<float*>(smem_raw);                       // [128][128]
    unsigned long long* Wp =
        reinterpret_cast<unsigned long long*>(smem_raw + 128 * 128 * 4);   // [128][32]

    const int tid = threadIdx.x;
    const int tx  = tid & 15;   // out-pair group: pairs {2tx,2tx+1} -> outs 4tx..4tx+3
    const int ty  = tid >> 4;   // node group: nodes 4ty..4ty+3  (ty 0..31)
    const int node_base = blockIdx.x * TILE_N;

    // stage W (row-major [128][64] floats == [128][32] f32x2 pairs)
    {
        const float4* W4  = reinterpret_cast<const float4*>(W);
        float4* Wp4 = reinterpret_cast<float4*>(Wp);
        #pragma unroll
        for (int i = tid; i < 128 * 64 / 4; i += NTHR) Wp4[i] = W4[i];
    }

    // stage A transposed: Ash[k][n] = concat(x, nsum)[node_base+n][k]
    // and zero the nsum float4s we consume (restores launch invariant).
    {
        float4* nsum4 = reinterpret_cast<float4*>(g_nsum);
        const float4 z = make_float4(0.f, 0.f, 0.f, 0.f);
        #pragma unroll
        for (int it = 0; it < 8; it++) {
            int idx = it * NTHR + tid;
            int n = idx & 127;         // lanes consecutive in n -> STS conflict-free
            int r = idx >> 7;          // k-quad 0..31
            int gn = node_base + n;
            float4 v = z;
            if (gn < n_nodes) {
                if (r < 16) {
                    v = x4[(long long)gn * 16 + r];
                } else {
                    float4* p = &nsum4[(long long)gn * 16 + (r - 16)];
                    v = *p;
                    *p = z;            // same thread, same addr: read-then-clear
                }
            }
            int k0 = 4 * r;
            Ash[(k0 + 0) * 128 + n] = v.x;
            Ash[(k0 + 1) * 128 + n] = v.y;
            Ash[(k0 + 2) * 128 + n] = v.z;
            Ash[(k0 + 3) * 128 + n] = v.w;
        }
    }
    __syncthreads();

    unsigned long long acc[4][2];
    #pragma unroll
    for (int i = 0; i < 4; i++) { acc[i][0] = 0ull; acc[i][1] = 0ull; }

    const float* ab = Ash + 4 * ty;
    const unsigned long long* wb = Wp + 2 * tx;

    #pragma unroll 8
    for (int k = 0; k < 128; k++) {
        float4 a = *reinterpret_cast<const float4*>(ab + k * 128);
        ulonglong2 w = *reinterpret_cast<const ulonglong2*>(wb + k * 32);
        unsigned long long ap0, ap1, ap2, ap3;
        asm("mov.b64 %0, {%1, %1};" : "=l"(ap0) : "f"(a.x));
        asm("mov.b64 %0, {%1, %1};" : "=l"(ap1) : "f"(a.y));
        asm("mov.b64 %0, {%1, %1};" : "=l"(ap2) : "f"(a.z));
        asm("mov.b64 %0, {%1, %1};" : "=l"(ap3) : "f"(a.w));
        asm("fma.rn.f32x2 %0, %1, %2, %0;" : "+l"(acc[0][0]) : "l"(ap0), "l"(w.x));
        asm("fma.rn.f32x2 %0, %1, %2, %0;" : "+l"(acc[0][1]) : "l"(ap0), "l"(w.y));
        asm("fma.rn.f32x2 %0, %1, %2, %0;" : "+l"(acc[1][0]) : "l"(ap1), "l"(w.x));
        asm("fma.rn.f32x2 %0, %1, %2, %0;" : "+l"(acc[1][1]) : "l"(ap1), "l"(w.y));
        asm("fma.rn.f32x2 %0, %1, %2, %0;" : "+l"(acc[2][0]) : "l"(ap2), "l"(w.x));
        asm("fma.rn.f32x2 %0, %1, %2, %0;" : "+l"(acc[2][1]) : "l"(ap2), "l"(w.y));
        asm("fma.rn.f32x2 %0, %1, %2, %0;" : "+l"(acc[3][0]) : "l"(ap3), "l"(w.x));
        asm("fma.rn.f32x2 %0, %1, %2, %0;" : "+l"(acc[3][1]) : "l"(ap3), "l"(w.y));
    }

    // epilogue: bias + LayerNorm + store
    const float4 bj = reinterpret_cast<const float4*>(b)[tx];
    const float4 gj = reinterpret_cast<const float4*>(gamma)[tx];
    const float4 ej = reinterpret_cast<const float4*>(beta)[tx];

    float val[4][4];
    #pragma unroll
    for (int i = 0; i < 4; i++) {
        val[i][0] = __uint_as_float((unsigned)(acc[i][0] & 0xffffffffull)) + bj.x;
        val[i][1] = __uint_as_float((unsigned)(acc[i][0] >> 32))           + bj.y;
        val[i][2] = __uint_as_float((unsigned)(acc[i][1] & 0xffffffffull)) + bj.z;
        val[i][3] = __uint_as_float((unsigned)(acc[i][1] >> 32))           + bj.w;
    }

    float s[4], ss[4];
    #pragma unroll
    for (int i = 0; i < 4; i++) {
        s[i]  = val[i][0] + val[i][1] + val[i][2] + val[i][3];
        ss[i] = val[i][0] * val[i][0] + val[i][1] * val[i][1]
              + val[i][2] * val[i][2] + val[i][3] * val[i][3];
    }
    // reduce across the 16 tx lanes (xor masks stay inside each 16-lane half)
    #pragma unroll
    for (int m = 1; m < 16; m <<= 1) {
        #pragma unroll
        for (int i = 0; i < 4; i++) {
            s[i]  += __shfl_xor_sync(0xFFFFFFFFu, s[i],  m);
            ss[i] += __shfl_xor_sync(0xFFFFFFFFu, ss[i], m);
        }
    }

    const float inv64 = 1.0f / 64.0f;
    #pragma unroll
    for (int i = 0; i < 4; i++) {
        float mu  = s[i] * inv64;
        float var = ss[i] * inv64 - mu * mu;
        float rs  = rsqrtf(var + LN_EPS);
        int gn = node_base + 4 * ty + i;
        if (gn < n_nodes) {
            float4 o;
            o.x = (val[i][0] - mu) * rs * gj.x + ej.x;
            o.y = (val[i][1] - mu) * rs * gj.y + ej.y;
            o.z = (val[i][2] - mu) * rs * gj.z + ej.z;
            o.w = (val[i][3] - mu) * rs * gj.w + ej.w;
            out4[(long long)gn * 16 + tx] = o;
        }
    }
}

// ---------------------------------------------------------------------------
// launch
// ---------------------------------------------------------------------------
extern "C" void kernel_launch(void* const* d_in, const int* in_sizes, int n_in,
                              void* d_out, int out_size) {
    const float* x     = (const float*)d_in[0];
    const void*  ei    = d_in[1];
    const float* W     = (const float*)d_in[2];
    const float* b     = (const float*)d_in[3];
    const float* gamma = (const float*)d_in[4];
    const float* beta  = (const float*)d_in[5];
    float* out = (float*)d_out;

    const int n_nodes = in_sizes[0] / D;      // 100000
    const int n_edges = in_sizes[1] / 2;      // 1000000

    // dynamic smem: A (64KB) + W pairs (32KB) = 96KB
    static_assert(128 * 128 * 4 + 128 * 32 * 8 == 98304, "smem layout");
    cudaFuncSetAttribute(gemm_ln_kernel,
                         cudaFuncAttributeMaxDynamicSharedMemorySize, 98304);

    // 1: scatter (16 lanes/edge, vectorized red.v4, per-block dtype detect)
    scatter_kernel<<<2368, 256>>>((const float4*)x, ei, n_edges, n_nodes);

    // 2: fused GEMM + LayerNorm (R2-proven loop, 512 threads, 50% occ)
    //    also restores g_nsum to all-zero for the next replay
    int gemm_blocks = (n_nodes + TILE_N - 1) / TILE_N;
    gemm_ln_kernel<<<gemm_blocks, NTHR, 98304>>>(
        (const float4*)x, W, b, gamma, beta, (float4*)out, n_nodes);
}

// round 6
// speedup vs baseline: 1.6555x; 1.6555x over previous
#include <cuda_runtime.h>
#include <cuda_bf16.h>
#include <cstdint>

// Problem constants (shapes fixed by the dataset)
#define N_NODES_MAX 100000
#define D 64
#define OUT 64
#define LN_EPS 1e-5f

// Scratch: neighbor_sum accumulator [N, D] — device global (no allocs allowed)
__device__ __align__(16) float g_nsum[N_NODES_MAX * D];
__device__ int g_is64;  // 1 if edge_index is int64, 0 if int32

// ---------------------------------------------------------------------------
// Kernel 0: zero the accumulator + (block 0) parallel dtype detection.
// Detection: if data is int32 pairs read as int64, high halves are ~uniform
// node indices; P(all 256 words look like valid int64) ~ 1e-1280.
// ---------------------------------------------------------------------------
__global__ void zero_detect_kernel(int n_float4,
                                   const long long* __restrict__ ei,
                                   int n_words, int n_nodes) {
    if (blockIdx.x == 0) {
        int bad = 0;
        int i = threadIdx.x;
        if (i < n_words) {
            long long v = ei[i];
            bad = (v < 0 || v >= (long long)n_nodes) ? 1 : 0;
        }
        int any_bad = __syncthreads_or(bad);
        if (threadIdx.x == 0) g_is64 = any_bad ? 0 : 1;
    }
    int i = blockIdx.x * blockDim.x + threadIdx.x;
    int stride = gridDim.x * blockDim.x;
    float4* p = reinterpret_cast<float4*>(g_nsum);
    float4 z = make_float4(0.f, 0.f, 0.f, 0.f);
    for (; i < n_float4; i += stride) p[i] = z;
}

// ---------------------------------------------------------------------------
// Kernel 1: scatter-add. 16 lanes per edge; lane handles float4 chunk `sub`.
// red.global.add.v4.f32: 4 floats per instruction, no return value.
// ---------------------------------------------------------------------------
__global__ void __launch_bounds__(256) scatter_kernel(
    const float4* __restrict__ x4,
    const void* __restrict__ ei_raw,
    int n_edges) {

    const long long* ei64 = reinterpret_cast<const long long*>(ei_raw);
    const int*       ei32 = reinterpret_cast<const int*>(ei_raw);
    const int is64 = g_is64;

    const int t   = blockIdx.x * blockDim.x + threadIdx.x;
    const int sub = t & 15;
    int e = t >> 4;
    const int estride = (gridDim.x * blockDim.x) >> 4;
    float4* __restrict__ nsum4 = reinterpret_cast<float4*>(g_nsum);

    if (is64) {
        for (; e < n_edges; e += estride) {
            long long row = ei64[e];
            long long col = ei64[n_edges + e];
            float4 v = x4[row * 16 + sub];
            float4* dst = &nsum4[col * 16 + sub];
            asm volatile("red.global.add.v4.f32 [%0], {%1, %2, %3, %4};"
                         :: "l"(dst), "f"(v.x), "f"(v.y), "f"(v.z), "f"(v.w)
                         : "memory");
        }
    } else {
        for (; e < n_edges; e += estride) {
            long long row = ei32[e];
            long long col = ei32[n_edges + e];
            float4 v = x4[row * 16 + sub];
            float4* dst = &nsum4[col * 16 + sub];
            asm volatile("red.global.add.v4.f32 [%0], {%1, %2, %3, %4};"
                         :: "l"(dst), "f"(v.x), "f"(v.y), "f"(v.z), "f"(v.w)
                         : "memory");
        }
    }
}

// ---------------------------------------------------------------------------
// Kernel 2: fused concat + Linear(128->64) + bias + LayerNorm.
// R2-proven inner loop at higher occupancy. NO read-modify-write on g_nsum
// (the RMW clear was the R4/R5 regression — same-address LDG->STG pairs
// serialize in the LSU).
//   block = 128 nodes x 64 outs, 512 threads, thread tile = 4 nodes x 4 outs.
// A staged transposed [k][n] (64KB); W staged as f32x2 pairs over OUT (32KB).
// Inner loop per k per thread:
//   1x LDS.128 (a: 4 nodes, broadcast)  +  1x LDS.128 (w: 2 f32x2 pairs)
//   4x mov.b64 {a,a}                    +  8x fma.rn.f32x2  (16 FMA lanes)
// smem 96KB -> 2 blocks/SM = 32 warps = 50% occ.
// ---------------------------------------------------------------------------
#define TILE_N 128
#define NTHR   512

__global__ void __launch_bounds__(NTHR, 2) gemm_ln_kernel(
    const float4* __restrict__ x4,
    const float*  __restrict__ W,
    const float*  __restrict__ b,
    const float*  __restrict__ gamma,
    const float*  __restrict__ beta,
    float4* __restrict__ out4,
    int n_nodes) {

    extern __shared__ char smem_raw[];
    float* Ash = reinterpret_cast<float*>(smem_raw);                       // [128][128]
    unsigned long long* Wp =
        reinterpret_cast<unsigned long long*>(smem_raw + 128 * 128 * 4);   // [128][32]

    const int tid = threadIdx.x;
    const int tx  = tid & 15;   // out-pair group: pairs {2tx,2tx+1} -> outs 4tx..4tx+3
    const int ty  = tid >> 4;   // node group: nodes 4ty..4ty+3  (ty 0..31)
    const int node_base = blockIdx.x * TILE_N;

    // stage W (row-major [128][64] floats == [128][32] f32x2 pairs)
    {
        const float4* W4  = reinterpret_cast<const float4*>(W);
        float4* Wp4 = reinterpret_cast<float4*>(Wp);
        #pragma unroll
        for (int i = tid; i < 128 * 64 / 4; i += NTHR) Wp4[i] = W4[i];
    }

    // stage A transposed: Ash[k][n] = concat(x, nsum)[node_base+n][k]
    // (pure reads — no RMW)
    {
        const float4* nsum4 = reinterpret_cast<const float4*>(g_nsum);
        #pragma unroll
        for (int it = 0; it < 8; it++) {
            int idx = it * NTHR + tid;
            int n = idx & 127;         // lanes consecutive in n -> STS conflict-free
            int r = idx >> 7;          // k-quad 0..31
            int gn = node_base + n;
            float4 v = make_float4(0.f, 0.f, 0.f, 0.f);
            if (gn < n_nodes)
                v = (r < 16) ? x4[(long long)gn * 16 + r]
                             : nsum4[(long long)gn * 16 + (r - 16)];
            int k0 = 4 * r;
            Ash[(k0 + 0) * 128 + n] = v.x;
            Ash[(k0 + 1) * 128 + n] = v.y;
            Ash[(k0 + 2) * 128 + n] = v.z;
            Ash[(k0 + 3) * 128 + n] = v.w;
        }
    }
    __syncthreads();

    unsigned long long acc[4][2];
    #pragma unroll
    for (int i = 0; i < 4; i++) { acc[i][0] = 0ull; acc[i][1] = 0ull; }

    const float* ab = Ash + 4 * ty;
    const unsigned long long* wb = Wp + 2 * tx;

    #pragma unroll 8
    for (int k = 0; k < 128; k++) {
        float4 a = *reinterpret_cast<const float4*>(ab + k * 128);
        ulonglong2 w = *reinterpret_cast<const ulonglong2*>(wb + k * 32);
        unsigned long long ap0, ap1, ap2, ap3;
        asm("mov.b64 %0, {%1, %1};" : "=l"(ap0) : "f"(a.x));
        asm("mov.b64 %0, {%1, %1};" : "=l"(ap1) : "f"(a.y));
        asm("mov.b64 %0, {%1, %1};" : "=l"(ap2) : "f"(a.z));
        asm("mov.b64 %0, {%1, %1};" : "=l"(ap3) : "f"(a.w));
        asm("fma.rn.f32x2 %0, %1, %2, %0;" : "+l"(acc[0][0]) : "l"(ap0), "l"(w.x));
        asm("fma.rn.f32x2 %0, %1, %2, %0;" : "+l"(acc[0][1]) : "l"(ap0), "l"(w.y));
        asm("fma.rn.f32x2 %0, %1, %2, %0;" : "+l"(acc[1][0]) : "l"(ap1), "l"(w.x));
        asm("fma.rn.f32x2 %0, %1, %2, %0;" : "+l"(acc[1][1]) : "l"(ap1), "l"(w.y));
        asm("fma.rn.f32x2 %0, %1, %2, %0;" : "+l"(acc[2][0]) : "l"(ap2), "l"(w.x));
        asm("fma.rn.f32x2 %0, %1, %2, %0;" : "+l"(acc[2][1]) : "l"(ap2), "l"(w.y));
        asm("fma.rn.f32x2 %0, %1, %2, %0;" : "+l"(acc[3][0]) : "l"(ap3), "l"(w.x));
        asm("fma.rn.f32x2 %0, %1, %2, %0;" : "+l"(acc[3][1]) : "l"(ap3), "l"(w.y));
    }

    // epilogue: bias + LayerNorm + store
    const float4 bj = reinterpret_cast<const float4*>(b)[tx];
    const float4 gj = reinterpret_cast<const float4*>(gamma)[tx];
    const float4 ej = reinterpret_cast<const float4*>(beta)[tx];

    float val[4][4];
    #pragma unroll
    for (int i = 0; i < 4; i++) {
        val[i][0] = __uint_as_float((unsigned)(acc[i][0] & 0xffffffffull)) + bj.x;
        val[i][1] = __uint_as_float((unsigned)(acc[i][0] >> 32))           + bj.y;
        val[i][2] = __uint_as_float((unsigned)(acc[i][1] & 0xffffffffull)) + bj.z;
        val[i][3] = __uint_as_float((unsigned)(acc[i][1] >> 32))           + bj.w;
    }

    float s[4], ss[4];
    #pragma unroll
    for (int i = 0; i < 4; i++) {
        s[i]  = val[i][0] + val[i][1] + val[i][2] + val[i][3];
        ss[i] = val[i][0] * val[i][0] + val[i][1] * val[i][1]
              + val[i][2] * val[i][2] + val[i][3] * val[i][3];
    }
    // reduce across the 16 tx lanes (xor masks stay inside each 16-lane half)
    #pragma unroll
    for (int m = 1; m < 16; m <<= 1) {
        #pragma unroll
        for (int i = 0; i < 4; i++) {
            s[i]  += __shfl_xor_sync(0xFFFFFFFFu, s[i],  m);
            ss[i] += __shfl_xor_sync(0xFFFFFFFFu, ss[i], m);
        }
    }

    const float inv64 = 1.0f / 64.0f;
    #pragma unroll
    for (int i = 0; i < 4; i++) {
        float mu  = s[i] * inv64;
        float var = ss[i] * inv64 - mu * mu;
        float rs  = rsqrtf(var + LN_EPS);
        int gn = node_base + 4 * ty + i;
        if (gn < n_nodes) {
            float4 o;
            o.x = (val[i][0] - mu) * rs * gj.x + ej.x;
            o.y = (val[i][1] - mu) * rs * gj.y + ej.y;
            o.z = (val[i][2] - mu) * rs * gj.z + ej.z;
            o.w = (val[i][3] - mu) * rs * gj.w + ej.w;
            out4[(long long)gn * 16 + tx] = o;
        }
    }
}

// ---------------------------------------------------------------------------
// launch
// ---------------------------------------------------------------------------
extern "C" void kernel_launch(void* const* d_in, const int* in_sizes, int n_in,
                              void* d_out, int out_size) {
    const float* x     = (const float*)d_in[0];
    const void*  ei    = d_in[1];
    const float* W     = (const float*)d_in[2];
    const float* b     = (const float*)d_in[3];
    const float* gamma = (const float*)d_in[4];
    const float* beta  = (const float*)d_in[5];
    float* out = (float*)d_out;

    const int n_nodes = in_sizes[0] / D;      // 100000
    const int n_edges = in_sizes[1] / 2;      // 1000000

    // dynamic smem: A (64KB) + W pairs (32KB) = 96KB
    static_assert(128 * 128 * 4 + 128 * 32 * 8 == 98304, "smem layout");
    cudaFuncSetAttribute(gemm_ln_kernel,
                         cudaFuncAttributeMaxDynamicSharedMemorySize, 98304);

    // 0: zero accumulator + parallel dtype detection (block 0)
    int n_words = n_edges / 2;
    if (n_words > 256) n_words = 256;
    const int n_f4 = n_nodes * D / 4;
    zero_detect_kernel<<<1184, 256>>>(n_f4, (const long long*)ei, n_words, n_nodes);

    // 1: scatter (16 lanes/edge, vectorized red.v4)
    scatter_kernel<<<2368, 256>>>((const float4*)x, ei, n_edges);

    // 2: fused GEMM + LayerNorm (R2 loop, 512 threads, 50% occ, no RMW)
    int gemm_blocks = (n_nodes + TILE_N - 1) / TILE_N;
    gemm_ln_kernel<<<gemm_blocks, NTHR, 98304>>>(
        (const float4*)x, W, b, gamma, beta, (float4*)out, n_nodes);
}